// round 1
// baseline (speedup 1.0000x reference)
#include <cuda_runtime.h>
#include <math.h>

#define B_   2
#define S_   2048
#define D_   1024
#define H_   16
#define DH_  64
#define DFF_ 4096
#define M_   (B_*S_)   // 4096 tokens

// ---------------- scratch (static device allocations; no cudaMalloc allowed) ----
__device__ float g_ln [M_ * D_];
__device__ float g_q  [M_ * D_];
__device__ float g_k  [M_ * D_];
__device__ float g_v  [M_ * D_];
__device__ float g_scores[(size_t)B_ * H_ * S_ * S_];   // 536 MB
__device__ float g_ctx[M_ * D_];
__device__ float g_h  [M_ * D_];
__device__ float g_ffn[(size_t)M_ * DFF_];              // 64 MB

// ---------------- LayerNorm: one block per row --------------------------------
__global__ void ln_kernel(const float* __restrict__ x,
                          const float* __restrict__ sc,
                          const float* __restrict__ sh,
                          float* __restrict__ out)
{
    int row = blockIdx.x;
    const float* xr = x + (size_t)row * D_;
    float* outr = out + (size_t)row * D_;

    float s = 0.f, s2 = 0.f;
    for (int j = threadIdx.x; j < D_; j += blockDim.x) {
        float v = xr[j];
        s += v; s2 += v * v;
    }
    __shared__ float rs[256], rs2[256];
    rs[threadIdx.x] = s; rs2[threadIdx.x] = s2;
    __syncthreads();
    for (int o = 128; o > 0; o >>= 1) {
        if (threadIdx.x < o) {
            rs [threadIdx.x] += rs [threadIdx.x + o];
            rs2[threadIdx.x] += rs2[threadIdx.x + o];
        }
        __syncthreads();
    }
    float mean = rs[0] * (1.0f / D_);
    float var  = rs2[0] * (1.0f / D_) - mean * mean;
    float inv  = rsqrtf(var + 1e-5f);
    for (int j = threadIdx.x; j < D_; j += blockDim.x)
        outr[j] = (xr[j] - mean) * inv * sc[j] + sh[j];
}

// ---------------- generic SGEMM: C = A(MxK) @ B(KxN) [+bias][gelu][+res] -------
// 64x64 tile, BK=16, 256 threads, 4x4 per thread. All dims divisible by 64/16.
__global__ void sgemm_kernel(const float* __restrict__ A,
                             const float* __restrict__ Bm,
                             const float* __restrict__ bias,   // may be null
                             const float* __restrict__ res,    // may be null
                             float* __restrict__ C,
                             int M, int N, int K, int gelu)
{
    const int BM = 64, BN = 64, BK = 16;
    __shared__ float As[BK][BM];
    __shared__ float Bs[BK][BN];

    int tid = threadIdx.x;
    int tx = tid & 15, ty = tid >> 4;
    int rowBase = blockIdx.y * BM, colBase = blockIdx.x * BN;

    float acc[4][4] = {};

    for (int k0 = 0; k0 < K; k0 += BK) {
        #pragma unroll
        for (int u = 0; u < 4; u++) {
            int id = tid * 4 + u;                  // 0..1023
            int r = id / BK, c = id % BK;          // A tile 64x16
            As[c][r] = A[(size_t)(rowBase + r) * K + k0 + c];
        }
        #pragma unroll
        for (int u = 0; u < 4; u++) {
            int id = tid * 4 + u;
            int r = id >> 6, c = id & 63;          // B tile 16x64
            Bs[r][c] = Bm[(size_t)(k0 + r) * N + colBase + c];
        }
        __syncthreads();
        #pragma unroll
        for (int kk = 0; kk < BK; kk++) {
            float a[4], b[4];
            #pragma unroll
            for (int i = 0; i < 4; i++) a[i] = As[kk][ty * 4 + i];
            #pragma unroll
            for (int j = 0; j < 4; j++) b[j] = Bs[kk][tx * 4 + j];
            #pragma unroll
            for (int i = 0; i < 4; i++)
                #pragma unroll
                for (int j = 0; j < 4; j++)
                    acc[i][j] += a[i] * b[j];
        }
        __syncthreads();
    }

    #pragma unroll
    for (int i = 0; i < 4; i++) {
        int r = rowBase + ty * 4 + i;
        #pragma unroll
        for (int j = 0; j < 4; j++) {
            int c = colBase + tx * 4 + j;
            float v = acc[i][j];
            if (bias) v += bias[c];
            if (gelu) {
                float t = 0.7978845608028654f * (v + 0.044715f * v * v * v);
                v = 0.5f * v * (1.f + tanhf(t));
            }
            if (res) v += res[(size_t)r * N + c];
            C[(size_t)r * N + c] = v;
        }
    }
}

// ---------------- attention scores: per (b,h), 64x64 tiles, K = 64 ------------
__global__ void scores_kernel(const float* __restrict__ q,
                              const float* __restrict__ k,
                              float* __restrict__ scores)
{
    int bh = blockIdx.z;
    int rowTile = blockIdx.y, colTile = blockIdx.x;
    if (colTile > rowTile) return;                 // fully masked block
    int b = bh / H_, h = bh % H_;
    const float* qb = q + (size_t)b * S_ * D_ + h * DH_;
    const float* kb = k + (size_t)b * S_ * D_ + h * DH_;
    float* sb = scores + (size_t)bh * S_ * S_;

    __shared__ float Qs[64][DH_ + 1];
    __shared__ float Ks[64][DH_ + 1];
    int tid = threadIdx.x;

    #pragma unroll
    for (int u = 0; u < 16; u++) {
        int id = tid + u * 256;
        int r = id >> 6, c = id & 63;
        Qs[r][c] = qb[(size_t)(rowTile * 64 + r) * D_ + c];
        Ks[r][c] = kb[(size_t)(colTile * 64 + r) * D_ + c];
    }
    __syncthreads();

    int tx = tid & 15, ty = tid >> 4;
    float acc[4][4] = {};
    #pragma unroll 8
    for (int kk = 0; kk < DH_; kk++) {
        float a[4], bv[4];
        #pragma unroll
        for (int i = 0; i < 4; i++) a[i]  = Qs[ty * 4 + i][kk];
        #pragma unroll
        for (int j = 0; j < 4; j++) bv[j] = Ks[tx * 4 + j][kk];
        #pragma unroll
        for (int i = 0; i < 4; i++)
            #pragma unroll
            for (int j = 0; j < 4; j++)
                acc[i][j] += a[i] * bv[j];
    }

    const float scale = 0.125f;   // 1/sqrt(64)
    #pragma unroll
    for (int i = 0; i < 4; i++) {
        int gi = rowTile * 64 + ty * 4 + i;
        #pragma unroll
        for (int j = 0; j < 4; j++) {
            int gj = colTile * 64 + tx * 4 + j;
            sb[(size_t)gi * S_ + gj] = (gj <= gi) ? acc[i][j] * scale : -1e30f;
        }
    }
}

// ---------------- causal row softmax (reads only the valid prefix) ------------
__global__ void softmax_kernel(float* __restrict__ scores)
{
    int r = blockIdx.x;                    // 0 .. B*H*S-1
    int bh = r / S_, i = r % S_;
    float* row = scores + (size_t)bh * S_ * S_ + (size_t)i * S_;
    int L = i + 1;
    __shared__ float red[128];

    float m = -1e30f;
    for (int j = threadIdx.x; j < L; j += 128) m = fmaxf(m, row[j]);
    red[threadIdx.x] = m; __syncthreads();
    for (int o = 64; o > 0; o >>= 1) {
        if (threadIdx.x < o) red[threadIdx.x] = fmaxf(red[threadIdx.x], red[threadIdx.x + o]);
        __syncthreads();
    }
    m = red[0];
    __syncthreads();

    float s = 0.f;
    for (int j = threadIdx.x; j < L; j += 128) s += __expf(row[j] - m);
    red[threadIdx.x] = s; __syncthreads();
    for (int o = 64; o > 0; o >>= 1) {
        if (threadIdx.x < o) red[threadIdx.x] += red[threadIdx.x + o];
        __syncthreads();
    }
    float inv = 1.f / red[0];
    for (int j = threadIdx.x; j < L; j += 128) row[j] = __expf(row[j] - m) * inv;
}

// ---------------- ctx = attn @ v : per (b,h), 64 rows x 64 cols per block ------
__global__ void ctx_kernel(const float* __restrict__ attn,
                           const float* __restrict__ v,
                           float* __restrict__ ctx)
{
    int bh = blockIdx.y;
    int rowTile = blockIdx.x;
    int b = bh / H_, h = bh % H_;
    const float* ab = attn + (size_t)bh * S_ * S_;
    const float* vb = v + (size_t)b * S_ * D_ + h * DH_;
    float* cb = ctx + (size_t)b * S_ * D_ + h * DH_;
    int rowBase = rowTile * 64;

    __shared__ float As[16][64];
    __shared__ float Bs[16][64];
    int tid = threadIdx.x;
    int tx = tid & 15, ty = tid >> 4;

    float acc[4][4] = {};
    int nkt = (rowBase + 64) / 16;          // only K-tiles up to the diagonal
    for (int kt = 0; kt < nkt; kt++) {
        int jBase = kt * 16;
        #pragma unroll
        for (int u = 0; u < 4; u++) {
            int id = tid + u * 256;
            int r = id >> 4, kk = id & 15;
            int gi = rowBase + r, gj = jBase + kk;
            As[kk][r] = (gj <= gi) ? ab[(size_t)gi * S_ + gj] : 0.f;
            int kv = id >> 6, n = id & 63;
            Bs[kv][n] = vb[(size_t)(jBase + kv) * D_ + n];
        }
        __syncthreads();
        #pragma unroll
        for (int kk = 0; kk < 16; kk++) {
            float a[4], bv[4];
            #pragma unroll
            for (int i = 0; i < 4; i++) a[i]  = As[kk][ty * 4 + i];
            #pragma unroll
            for (int j = 0; j < 4; j++) bv[j] = Bs[kk][tx * 4 + j];
            #pragma unroll
            for (int i = 0; i < 4; i++)
                #pragma unroll
                for (int j = 0; j < 4; j++)
                    acc[i][j] += a[i] * bv[j];
        }
        __syncthreads();
    }

    #pragma unroll
    for (int i = 0; i < 4; i++) {
        int r = rowBase + ty * 4 + i;
        #pragma unroll
        for (int j = 0; j < 4; j++)
            cb[(size_t)r * D_ + tx * 4 + j] = acc[i][j];
    }
}

// ---------------- launcher -----------------------------------------------------
extern "C" void kernel_launch(void* const* d_in, const int* in_sizes, int n_in,
                              void* d_out, int out_size)
{
    const float* x     = (const float*)d_in[0];
    const float* ln1_s = (const float*)d_in[1];
    const float* ln1_b = (const float*)d_in[2];
    const float* wq    = (const float*)d_in[3];
    const float* wk    = (const float*)d_in[4];
    const float* wv    = (const float*)d_in[5];
    const float* wo    = (const float*)d_in[6];
    const float* bo    = (const float*)d_in[7];
    const float* ln2_s = (const float*)d_in[8];
    const float* ln2_b = (const float*)d_in[9];
    const float* w1    = (const float*)d_in[10];
    const float* b1    = (const float*)d_in[11];
    const float* w2    = (const float*)d_in[12];
    const float* b2    = (const float*)d_in[13];
    float* out = (float*)d_out;

    float *ln, *q, *k, *v, *sc, *ctx, *h, *ffn;
    cudaGetSymbolAddress((void**)&ln,  g_ln);
    cudaGetSymbolAddress((void**)&q,   g_q);
    cudaGetSymbolAddress((void**)&k,   g_k);
    cudaGetSymbolAddress((void**)&v,   g_v);
    cudaGetSymbolAddress((void**)&sc,  g_scores);
    cudaGetSymbolAddress((void**)&ctx, g_ctx);
    cudaGetSymbolAddress((void**)&h,   g_h);
    cudaGetSymbolAddress((void**)&ffn, g_ffn);

    // 1) ln1(x)
    ln_kernel<<<M_, 256>>>(x, ln1_s, ln1_b, ln);

    // 2) q/k/v projections
    dim3 gp(D_ / 64, M_ / 64);
    sgemm_kernel<<<gp, 256>>>(ln, wq, nullptr, nullptr, q, M_, D_, D_, 0);
    sgemm_kernel<<<gp, 256>>>(ln, wk, nullptr, nullptr, k, M_, D_, D_, 0);
    sgemm_kernel<<<gp, 256>>>(ln, wv, nullptr, nullptr, v, M_, D_, D_, 0);

    // 3) attention
    dim3 gs(S_ / 64, S_ / 64, B_ * H_);
    scores_kernel<<<gs, 256>>>(q, k, sc);
    softmax_kernel<<<B_ * H_ * S_, 128>>>(sc);
    dim3 gc(S_ / 64, B_ * H_);
    ctx_kernel<<<gc, 256>>>(sc, v, ctx);

    // 4) output projection + residual -> h
    sgemm_kernel<<<gp, 256>>>(ctx, wo, bo, x, h, M_, D_, D_, 0);

    // 5) ln2(h)
    ln_kernel<<<M_, 256>>>(h, ln2_s, ln2_b, ln);

    // 6) FFN
    dim3 gf1(DFF_ / 64, M_ / 64);
    sgemm_kernel<<<gf1, 256>>>(ln, w1, b1, nullptr, ffn, M_, DFF_, D_, 1);
    sgemm_kernel<<<gp, 256>>>(ffn, w2, b2, h, out, M_, D_, DFF_, 0);
}

// round 2
// speedup vs baseline: 2.6836x; 2.6836x over previous
#include <cuda_runtime.h>
#include <math.h>

#define B_   2
#define S_   2048
#define D_   1024
#define H_   16
#define DH_  64
#define DFF_ 4096
#define M_   (B_*S_)   // 4096 tokens

// ---------------- scratch (static device allocations; no cudaMalloc allowed) ----
__device__ float g_ln [M_ * D_];
__device__ float g_q  [M_ * D_];
__device__ float g_k  [M_ * D_];
__device__ float g_v  [M_ * D_];
__device__ float g_scores[(size_t)B_ * H_ * S_ * S_];   // 536 MB
__device__ float g_ctx[M_ * D_];
__device__ float g_h  [M_ * D_];
__device__ float g_ffn[(size_t)M_ * DFF_];              // 64 MB

// ---------------- LayerNorm: one block per row --------------------------------
__global__ void ln_kernel(const float* __restrict__ x,
                          const float* __restrict__ sc,
                          const float* __restrict__ sh,
                          float* __restrict__ out)
{
    int row = blockIdx.x;
    const float* xr = x + (size_t)row * D_;
    float* outr = out + (size_t)row * D_;

    float s = 0.f, s2 = 0.f;
    for (int j = threadIdx.x; j < D_; j += blockDim.x) {
        float v = xr[j];
        s += v; s2 += v * v;
    }
    __shared__ float rs[256], rs2[256];
    rs[threadIdx.x] = s; rs2[threadIdx.x] = s2;
    __syncthreads();
    for (int o = 128; o > 0; o >>= 1) {
        if (threadIdx.x < o) {
            rs [threadIdx.x] += rs [threadIdx.x + o];
            rs2[threadIdx.x] += rs2[threadIdx.x + o];
        }
        __syncthreads();
    }
    float mean = rs[0] * (1.0f / D_);
    float var  = rs2[0] * (1.0f / D_) - mean * mean;
    float inv  = rsqrtf(var + 1e-5f);
    for (int j = threadIdx.x; j < D_; j += blockDim.x)
        outr[j] = (xr[j] - mean) * inv * sc[j] + sh[j];
}

// ---------------- TF32 tensor-core GEMM --------------------------------------
// C(MxN) = A(MxK) @ B(KxN) [+bias][gelu][+res], all row-major fp32.
// 128x128 CTA tile, BK=16, 256 threads (8 warps, each 64x32),
// cp.async 2-stage pipeline, mma.sync m16n8k8 tf32.

__device__ __forceinline__ unsigned f2tf32(float x) {
    unsigned r;
    asm("cvt.rna.tf32.f32 %0, %1;" : "=r"(r) : "f"(x));
    return r;
}

__device__ __forceinline__ void mma_tf32(float* c, const unsigned* a, const unsigned* b) {
    asm volatile(
        "mma.sync.aligned.m16n8k8.row.col.f32.tf32.tf32.f32 "
        "{%0,%1,%2,%3}, {%4,%5,%6,%7}, {%8,%9}, {%0,%1,%2,%3};"
        : "+f"(c[0]), "+f"(c[1]), "+f"(c[2]), "+f"(c[3])
        : "r"(a[0]), "r"(a[1]), "r"(a[2]), "r"(a[3]), "r"(b[0]), "r"(b[1]));
}

__device__ __forceinline__ void cpasync16(float* smem, const float* gmem) {
    unsigned s = (unsigned)__cvta_generic_to_shared(smem);
    asm volatile("cp.async.cg.shared.global [%0], [%1], 16;" :: "r"(s), "l"(gmem));
}

#define AS_STRIDE 20    // 16 + 4 pad -> fragment banks 4m+k, conflict-free
#define BS_STRIDE 136   // 128 + 8 pad -> fragment banks 8t+g, conflict-free
#define AS_BUF (128 * AS_STRIDE)
#define BS_BUF (16 * BS_STRIDE)

__global__ __launch_bounds__(256, 2)
void sgemm_tf32_kernel(const float* __restrict__ A,
                       const float* __restrict__ Bm,
                       const float* __restrict__ bias,   // may be null
                       const float* __restrict__ res,    // may be null
                       float* __restrict__ C,
                       int M, int N, int K, int gelu)
{
    __shared__ float As[2 * AS_BUF];   // 20 KB
    __shared__ float Bs[2 * BS_BUF];   // 17 KB

    const int tid  = threadIdx.x;
    const int lane = tid & 31;
    const int warp = tid >> 5;
    const int g    = lane >> 2;     // 0..7
    const int t    = lane & 3;      // 0..3
    const int warpRow = warp >> 2;  // 0..1 -> 64 rows each
    const int warpCol = warp & 3;   // 0..3 -> 32 cols each

    const int rowBase = blockIdx.y * 128;
    const int colBase = blockIdx.x * 128;

    float acc[4][4][4];
    #pragma unroll
    for (int i = 0; i < 4; i++)
        #pragma unroll
        for (int j = 0; j < 4; j++)
            #pragma unroll
            for (int r = 0; r < 4; r++) acc[i][j][r] = 0.f;

    const int nIter = K / 16;

    // --- prefetch stage 0 ---
    {
        int k0 = 0;
        #pragma unroll
        for (int u = 0; u < 2; u++) {
            int id = tid + u * 256;
            int r = id >> 2, kc = (id & 3) * 4;
            cpasync16(&As[r * AS_STRIDE + kc],
                      &A[(size_t)(rowBase + r) * K + k0 + kc]);
        }
        #pragma unroll
        for (int u = 0; u < 2; u++) {
            int id = tid + u * 256;
            int r = id >> 5, nc = (id & 31) * 4;
            cpasync16(&Bs[r * BS_STRIDE + nc],
                      &Bm[(size_t)(k0 + r) * N + colBase + nc]);
        }
        asm volatile("cp.async.commit_group;");
    }

    int buf = 0;
    for (int it = 0; it < nIter; ++it) {
        if (it + 1 < nIter) {
            int k0 = (it + 1) * 16;
            float* Asn = As + (buf ^ 1) * AS_BUF;
            float* Bsn = Bs + (buf ^ 1) * BS_BUF;
            #pragma unroll
            for (int u = 0; u < 2; u++) {
                int id = tid + u * 256;
                int r = id >> 2, kc = (id & 3) * 4;
                cpasync16(&Asn[r * AS_STRIDE + kc],
                          &A[(size_t)(rowBase + r) * K + k0 + kc]);
            }
            #pragma unroll
            for (int u = 0; u < 2; u++) {
                int id = tid + u * 256;
                int r = id >> 5, nc = (id & 31) * 4;
                cpasync16(&Bsn[r * BS_STRIDE + nc],
                          &Bm[(size_t)(k0 + r) * N + colBase + nc]);
            }
            asm volatile("cp.async.commit_group;");
            asm volatile("cp.async.wait_group 1;");
        } else {
            asm volatile("cp.async.wait_group 0;");
        }
        __syncthreads();

        const float* As_ = As + buf * AS_BUF;
        const float* Bs_ = Bs + buf * BS_BUF;

        #pragma unroll
        for (int ks = 0; ks < 2; ks++) {
            const int k = ks * 8;
            unsigned afr[4][4], bfr[4][2];
            #pragma unroll
            for (int mt = 0; mt < 4; mt++) {
                int m = warpRow * 64 + mt * 16 + g;
                afr[mt][0] = f2tf32(As_[m * AS_STRIDE + k + t]);
                afr[mt][1] = f2tf32(As_[(m + 8) * AS_STRIDE + k + t]);
                afr[mt][2] = f2tf32(As_[m * AS_STRIDE + k + t + 4]);
                afr[mt][3] = f2tf32(As_[(m + 8) * AS_STRIDE + k + t + 4]);
            }
            #pragma unroll
            for (int nt = 0; nt < 4; nt++) {
                int n = warpCol * 32 + nt * 8 + g;
                bfr[nt][0] = f2tf32(Bs_[(k + t) * BS_STRIDE + n]);
                bfr[nt][1] = f2tf32(Bs_[(k + t + 4) * BS_STRIDE + n]);
            }
            #pragma unroll
            for (int mt = 0; mt < 4; mt++)
                #pragma unroll
                for (int nt = 0; nt < 4; nt++)
                    mma_tf32(acc[mt][nt], afr[mt], bfr[nt]);
        }
        __syncthreads();
        buf ^= 1;
    }

    // --- epilogue ---
    #pragma unroll
    for (int mt = 0; mt < 4; mt++) {
        #pragma unroll
        for (int nt = 0; nt < 4; nt++) {
            int r0 = rowBase + warpRow * 64 + mt * 16 + g;
            int c0 = colBase + warpCol * 32 + nt * 8 + 2 * t;
            #pragma unroll
            for (int e = 0; e < 4; e++) {
                int r = r0 + (e >> 1) * 8;
                int c = c0 + (e & 1);
                float v = acc[mt][nt][e];
                if (bias) v += bias[c];
                if (gelu) {
                    float tt = 0.7978845608028654f * (v + 0.044715f * v * v * v);
                    v = 0.5f * v * (1.f + tanhf(tt));
                }
                if (res) v += res[(size_t)r * N + c];
                C[(size_t)r * N + c] = v;
            }
        }
    }
}

// ---------------- attention scores: per (b,h), 64x64 tiles, K = 64 ------------
__global__ void scores_kernel(const float* __restrict__ q,
                              const float* __restrict__ k,
                              float* __restrict__ scores)
{
    int bh = blockIdx.z;
    int rowTile = blockIdx.y, colTile = blockIdx.x;
    if (colTile > rowTile) return;                 // fully masked block
    int b = bh / H_, h = bh % H_;
    const float* qb = q + (size_t)b * S_ * D_ + h * DH_;
    const float* kb = k + (size_t)b * S_ * D_ + h * DH_;
    float* sb = scores + (size_t)bh * S_ * S_;

    __shared__ float Qs[64][DH_ + 1];
    __shared__ float Ks[64][DH_ + 1];
    int tid = threadIdx.x;

    #pragma unroll
    for (int u = 0; u < 16; u++) {
        int id = tid + u * 256;
        int r = id >> 6, c = id & 63;
        Qs[r][c] = qb[(size_t)(rowTile * 64 + r) * D_ + c];
        Ks[r][c] = kb[(size_t)(colTile * 64 + r) * D_ + c];
    }
    __syncthreads();

    int tx = tid & 15, ty = tid >> 4;
    float acc[4][4] = {};
    #pragma unroll 8
    for (int kk = 0; kk < DH_; kk++) {
        float a[4], bv[4];
        #pragma unroll
        for (int i = 0; i < 4; i++) a[i]  = Qs[ty * 4 + i][kk];
        #pragma unroll
        for (int j = 0; j < 4; j++) bv[j] = Ks[tx * 4 + j][kk];
        #pragma unroll
        for (int i = 0; i < 4; i++)
            #pragma unroll
            for (int j = 0; j < 4; j++)
                acc[i][j] += a[i] * bv[j];
    }

    const float scale = 0.125f;   // 1/sqrt(64)
    #pragma unroll
    for (int i = 0; i < 4; i++) {
        int gi = rowTile * 64 + ty * 4 + i;
        #pragma unroll
        for (int j = 0; j < 4; j++) {
            int gj = colTile * 64 + tx * 4 + j;
            sb[(size_t)gi * S_ + gj] = (gj <= gi) ? acc[i][j] * scale : -1e30f;
        }
    }
}

// ---------------- causal row softmax (reads only the valid prefix) ------------
__global__ void softmax_kernel(float* __restrict__ scores)
{
    int r = blockIdx.x;                    // 0 .. B*H*S-1
    int bh = r / S_, i = r % S_;
    float* row = scores + (size_t)bh * S_ * S_ + (size_t)i * S_;
    int L = i + 1;
    __shared__ float red[128];

    float m = -1e30f;
    for (int j = threadIdx.x; j < L; j += 128) m = fmaxf(m, row[j]);
    red[threadIdx.x] = m; __syncthreads();
    for (int o = 64; o > 0; o >>= 1) {
        if (threadIdx.x < o) red[threadIdx.x] = fmaxf(red[threadIdx.x], red[threadIdx.x + o]);
        __syncthreads();
    }
    m = red[0];
    __syncthreads();

    float s = 0.f;
    for (int j = threadIdx.x; j < L; j += 128) s += __expf(row[j] - m);
    red[threadIdx.x] = s; __syncthreads();
    for (int o = 64; o > 0; o >>= 1) {
        if (threadIdx.x < o) red[threadIdx.x] += red[threadIdx.x + o];
        __syncthreads();
    }
    float inv = 1.f / red[0];
    for (int j = threadIdx.x; j < L; j += 128) row[j] = __expf(row[j] - m) * inv;
}

// ---------------- ctx = attn @ v : per (b,h), 64 rows x 64 cols per block ------
__global__ void ctx_kernel(const float* __restrict__ attn,
                           const float* __restrict__ v,
                           float* __restrict__ ctx)
{
    int bh = blockIdx.y;
    int rowTile = blockIdx.x;
    int b = bh / H_, h = bh % H_;
    const float* ab = attn + (size_t)bh * S_ * S_;
    const float* vb = v + (size_t)b * S_ * D_ + h * DH_;
    float* cb = ctx + (size_t)b * S_ * D_ + h * DH_;
    int rowBase = rowTile * 64;

    __shared__ float As[16][64];
    __shared__ float Bs[16][64];
    int tid = threadIdx.x;
    int tx = tid & 15, ty = tid >> 4;

    float acc[4][4] = {};
    int nkt = (rowBase + 64) / 16;          // only K-tiles up to the diagonal
    for (int kt = 0; kt < nkt; kt++) {
        int jBase = kt * 16;
        #pragma unroll
        for (int u = 0; u < 4; u++) {
            int id = tid + u * 256;
            int r = id >> 4, kk = id & 15;
            int gi = rowBase + r, gj = jBase + kk;
            As[kk][r] = (gj <= gi) ? ab[(size_t)gi * S_ + gj] : 0.f;
            int kv = id >> 6, n = id & 63;
            Bs[kv][n] = vb[(size_t)(jBase + kv) * D_ + n];
        }
        __syncthreads();
        #pragma unroll
        for (int kk = 0; kk < 16; kk++) {
            float a[4], bv[4];
            #pragma unroll
            for (int i = 0; i < 4; i++) a[i]  = As[kk][ty * 4 + i];
            #pragma unroll
            for (int j = 0; j < 4; j++) bv[j] = Bs[kk][tx * 4 + j];
            #pragma unroll
            for (int i = 0; i < 4; i++)
                #pragma unroll
                for (int j = 0; j < 4; j++)
                    acc[i][j] += a[i] * bv[j];
        }
        __syncthreads();
    }

    #pragma unroll
    for (int i = 0; i < 4; i++) {
        int r = rowBase + ty * 4 + i;
        #pragma unroll
        for (int j = 0; j < 4; j++)
            cb[(size_t)r * D_ + tx * 4 + j] = acc[i][j];
    }
}

// ---------------- launcher -----------------------------------------------------
extern "C" void kernel_launch(void* const* d_in, const int* in_sizes, int n_in,
                              void* d_out, int out_size)
{
    const float* x     = (const float*)d_in[0];
    const float* ln1_s = (const float*)d_in[1];
    const float* ln1_b = (const float*)d_in[2];
    const float* wq    = (const float*)d_in[3];
    const float* wk    = (const float*)d_in[4];
    const float* wv    = (const float*)d_in[5];
    const float* wo    = (const float*)d_in[6];
    const float* bo    = (const float*)d_in[7];
    const float* ln2_s = (const float*)d_in[8];
    const float* ln2_b = (const float*)d_in[9];
    const float* w1    = (const float*)d_in[10];
    const float* b1    = (const float*)d_in[11];
    const float* w2    = (const float*)d_in[12];
    const float* b2    = (const float*)d_in[13];
    float* out = (float*)d_out;

    float *ln, *q, *k, *v, *sc, *ctx, *h, *ffn;
    cudaGetSymbolAddress((void**)&ln,  g_ln);
    cudaGetSymbolAddress((void**)&q,   g_q);
    cudaGetSymbolAddress((void**)&k,   g_k);
    cudaGetSymbolAddress((void**)&v,   g_v);
    cudaGetSymbolAddress((void**)&sc,  g_scores);
    cudaGetSymbolAddress((void**)&ctx, g_ctx);
    cudaGetSymbolAddress((void**)&h,   g_h);
    cudaGetSymbolAddress((void**)&ffn, g_ffn);

    // 1) ln1(x)
    ln_kernel<<<M_, 256>>>(x, ln1_s, ln1_b, ln);

    // 2) q/k/v projections (tf32 tensor cores)
    dim3 gp(D_ / 128, M_ / 128);
    sgemm_tf32_kernel<<<gp, 256>>>(ln, wq, nullptr, nullptr, q, M_, D_, D_, 0);
    sgemm_tf32_kernel<<<gp, 256>>>(ln, wk, nullptr, nullptr, k, M_, D_, D_, 0);
    sgemm_tf32_kernel<<<gp, 256>>>(ln, wv, nullptr, nullptr, v, M_, D_, D_, 0);

    // 3) attention
    dim3 gs(S_ / 64, S_ / 64, B_ * H_);
    scores_kernel<<<gs, 256>>>(q, k, sc);
    softmax_kernel<<<B_ * H_ * S_, 128>>>(sc);
    dim3 gc(S_ / 64, B_ * H_);
    ctx_kernel<<<gc, 256>>>(sc, v, ctx);

    // 4) output projection + residual -> h
    sgemm_tf32_kernel<<<gp, 256>>>(ctx, wo, bo, x, h, M_, D_, D_, 0);

    // 5) ln2(h)
    ln_kernel<<<M_, 256>>>(h, ln2_s, ln2_b, ln);

    // 6) FFN
    dim3 gf1(DFF_ / 128, M_ / 128);
    sgemm_tf32_kernel<<<gf1, 256>>>(ln, w1, b1, nullptr, ffn, M_, DFF_, D_, 1);
    sgemm_tf32_kernel<<<gp, 256>>>(ffn, w2, b2, h, out, M_, D_, DFF_, 0);
}

// round 3
// speedup vs baseline: 4.6034x; 1.7154x over previous
#include <cuda_runtime.h>
#include <math.h>

#define B_   2
#define S_   2048
#define D_   1024
#define H_   16
#define DH_  64
#define DFF_ 4096
#define M_   (B_*S_)   // 4096 tokens

// ---------------- scratch (static device allocations; no cudaMalloc allowed) ----
__device__ float g_ln [M_ * D_];
__device__ float g_q  [M_ * D_];
__device__ float g_k  [M_ * D_];
__device__ float g_v  [M_ * D_];
__device__ float g_ctx[M_ * D_];
__device__ float g_h  [M_ * D_];
__device__ float g_ffn[(size_t)M_ * DFF_];              // 64 MB
__device__ float g_pool[12 * 1024 * 1024];              // rounded weights, 48 MB

// ---------------- helpers ------------------------------------------------------
__device__ __forceinline__ unsigned f2tf32(float x) {
    unsigned r;
    asm("cvt.rna.tf32.f32 %0, %1;" : "=r"(r) : "f"(x));
    return r;
}
__device__ __forceinline__ float rnd_tf32(float x) {
    return __uint_as_float(f2tf32(x));
}
__device__ __forceinline__ void mma_tf32(float* c, const unsigned* a, const unsigned* b) {
    asm volatile(
        "mma.sync.aligned.m16n8k8.row.col.f32.tf32.tf32.f32 "
        "{%0,%1,%2,%3}, {%4,%5,%6,%7}, {%8,%9}, {%0,%1,%2,%3};"
        : "+f"(c[0]), "+f"(c[1]), "+f"(c[2]), "+f"(c[3])
        : "r"(a[0]), "r"(a[1]), "r"(a[2]), "r"(a[3]), "r"(b[0]), "r"(b[1]));
}
__device__ __forceinline__ void cpasync16(float* smem, const float* gmem) {
    unsigned s = (unsigned)__cvta_generic_to_shared(smem);
    asm volatile("cp.async.cg.shared.global [%0], [%1], 16;" :: "r"(s), "l"(gmem));
}

// ---------------- pre-round weights to tf32 ------------------------------------
__global__ void round_tf32_kernel(const float* __restrict__ in,
                                  float* __restrict__ out, int n4)
{
    int i = blockIdx.x * 256 + threadIdx.x;
    if (i < n4) {
        float4 a = ((const float4*)in)[i];
        a.x = rnd_tf32(a.x); a.y = rnd_tf32(a.y);
        a.z = rnd_tf32(a.z); a.w = rnd_tf32(a.w);
        ((float4*)out)[i] = a;
    }
}

// ---------------- LayerNorm (output tf32-rounded: feeds GEMM A only) ----------
__global__ void ln_kernel(const float* __restrict__ x,
                          const float* __restrict__ sc,
                          const float* __restrict__ sh,
                          float* __restrict__ out)
{
    int row = blockIdx.x;
    const float* xr = x + (size_t)row * D_;
    float* outr = out + (size_t)row * D_;

    float s = 0.f, s2 = 0.f;
    for (int j = threadIdx.x; j < D_; j += blockDim.x) {
        float v = xr[j];
        s += v; s2 += v * v;
    }
    __shared__ float rs[256], rs2[256];
    rs[threadIdx.x] = s; rs2[threadIdx.x] = s2;
    __syncthreads();
    for (int o = 128; o > 0; o >>= 1) {
        if (threadIdx.x < o) {
            rs [threadIdx.x] += rs [threadIdx.x + o];
            rs2[threadIdx.x] += rs2[threadIdx.x + o];
        }
        __syncthreads();
    }
    float mean = rs[0] * (1.0f / D_);
    float var  = rs2[0] * (1.0f / D_) - mean * mean;
    float inv  = rsqrtf(var + 1e-5f);
    for (int j = threadIdx.x; j < D_; j += blockDim.x)
        outr[j] = rnd_tf32((xr[j] - mean) * inv * sc[j] + sh[j]);
}

// ---------------- TF32 tensor-core GEMM (operands pre-rounded) -----------------
#define AS_STRIDE 20
#define BS_STRIDE 136
#define AS_BUF (128 * AS_STRIDE)
#define BS_BUF (16 * BS_STRIDE)

__global__ __launch_bounds__(256, 2)
void sgemm_tf32_kernel(const float* __restrict__ A,
                       const float* __restrict__ Bm,
                       const float* __restrict__ bias,   // may be null
                       const float* __restrict__ res,    // may be null
                       float* __restrict__ C,
                       int M, int N, int K, int gelu, int roundOut)
{
    __shared__ float As[2 * AS_BUF];
    __shared__ float Bs[2 * BS_BUF];

    const int tid  = threadIdx.x;
    const int lane = tid & 31;
    const int warp = tid >> 5;
    const int g    = lane >> 2;
    const int t    = lane & 3;
    const int warpRow = warp >> 2;
    const int warpCol = warp & 3;

    const int rowBase = blockIdx.y * 128;
    const int colBase = blockIdx.x * 128;

    float acc[4][4][4];
    #pragma unroll
    for (int i = 0; i < 4; i++)
        #pragma unroll
        for (int j = 0; j < 4; j++)
            #pragma unroll
            for (int r = 0; r < 4; r++) acc[i][j][r] = 0.f;

    const int nIter = K / 16;

    {
        #pragma unroll
        for (int u = 0; u < 2; u++) {
            int id = tid + u * 256;
            int r = id >> 2, kc = (id & 3) * 4;
            cpasync16(&As[r * AS_STRIDE + kc], &A[(size_t)(rowBase + r) * K + kc]);
        }
        #pragma unroll
        for (int u = 0; u < 2; u++) {
            int id = tid + u * 256;
            int r = id >> 5, nc = (id & 31) * 4;
            cpasync16(&Bs[r * BS_STRIDE + nc], &Bm[(size_t)r * N + colBase + nc]);
        }
        asm volatile("cp.async.commit_group;");
    }

    int buf = 0;
    for (int it = 0; it < nIter; ++it) {
        if (it + 1 < nIter) {
            int k0 = (it + 1) * 16;
            float* Asn = As + (buf ^ 1) * AS_BUF;
            float* Bsn = Bs + (buf ^ 1) * BS_BUF;
            #pragma unroll
            for (int u = 0; u < 2; u++) {
                int id = tid + u * 256;
                int r = id >> 2, kc = (id & 3) * 4;
                cpasync16(&Asn[r * AS_STRIDE + kc],
                          &A[(size_t)(rowBase + r) * K + k0 + kc]);
            }
            #pragma unroll
            for (int u = 0; u < 2; u++) {
                int id = tid + u * 256;
                int r = id >> 5, nc = (id & 31) * 4;
                cpasync16(&Bsn[r * BS_STRIDE + nc],
                          &Bm[(size_t)(k0 + r) * N + colBase + nc]);
            }
            asm volatile("cp.async.commit_group;");
            asm volatile("cp.async.wait_group 1;");
        } else {
            asm volatile("cp.async.wait_group 0;");
        }
        __syncthreads();

        const float* As_ = As + buf * AS_BUF;
        const float* Bs_ = Bs + buf * BS_BUF;

        #pragma unroll
        for (int ks = 0; ks < 2; ks++) {
            const int k = ks * 8;
            unsigned afr[4][4], bfr[4][2];
            #pragma unroll
            for (int mt = 0; mt < 4; mt++) {
                int m = warpRow * 64 + mt * 16 + g;
                afr[mt][0] = __float_as_uint(As_[m * AS_STRIDE + k + t]);
                afr[mt][1] = __float_as_uint(As_[(m + 8) * AS_STRIDE + k + t]);
                afr[mt][2] = __float_as_uint(As_[m * AS_STRIDE + k + t + 4]);
                afr[mt][3] = __float_as_uint(As_[(m + 8) * AS_STRIDE + k + t + 4]);
            }
            #pragma unroll
            for (int nt = 0; nt < 4; nt++) {
                int n = warpCol * 32 + nt * 8 + g;
                bfr[nt][0] = __float_as_uint(Bs_[(k + t) * BS_STRIDE + n]);
                bfr[nt][1] = __float_as_uint(Bs_[(k + t + 4) * BS_STRIDE + n]);
            }
            #pragma unroll
            for (int mt = 0; mt < 4; mt++)
                #pragma unroll
                for (int nt = 0; nt < 4; nt++)
                    mma_tf32(acc[mt][nt], afr[mt], bfr[nt]);
        }
        __syncthreads();
        buf ^= 1;
    }

    #pragma unroll
    for (int mt = 0; mt < 4; mt++) {
        #pragma unroll
        for (int nt = 0; nt < 4; nt++) {
            int r0 = rowBase + warpRow * 64 + mt * 16 + g;
            int c0 = colBase + warpCol * 32 + nt * 8 + 2 * t;
            #pragma unroll
            for (int e = 0; e < 4; e++) {
                int r = r0 + (e >> 1) * 8;
                int c = c0 + (e & 1);
                float v = acc[mt][nt][e];
                if (bias) v += bias[c];
                if (gelu) {
                    // 0.5v(1+tanh(t)) == v * sigmoid(2t)
                    float tt = 1.5957691216057308f * v + 0.0713548162726009f * v * v * v;
                    v = __fdividef(v, 1.f + __expf(-tt));
                }
                if (res) v += res[(size_t)r * N + c];
                if (roundOut) v = rnd_tf32(v);
                C[(size_t)r * N + c] = v;
            }
        }
    }
}

// ---------------- fused flash attention (causal, tf32 mma) ---------------------
// grid (16, 32): x -> q-tile of 128 rows (reversed for scheduling), y -> (b,h)
#define SK 68
#define SV 72
#define FLASH_SMEM ((128*SK + 64*SK + 64*SV) * 4)

__global__ __launch_bounds__(256)
void flash_attn_kernel(const float* __restrict__ q, const float* __restrict__ k,
                       const float* __restrict__ v, float* __restrict__ ctx)
{
    extern __shared__ float sm[];
    float* Ps = sm;                       // 128 x SK (Q prologue, then P)
    float* Ks = sm + 128 * SK;            // 64 x SK
    float* Vs = sm + 128 * SK + 64 * SK;  // 64 x SV

    const int qt = (int)(gridDim.x - 1) - (int)blockIdx.x;   // big tiles first
    const int bh = blockIdx.y;
    const int b = bh >> 4, h = bh & 15;
    const float* qb = q + (size_t)b * S_ * D_ + h * DH_;
    const float* kb = k + (size_t)b * S_ * D_ + h * DH_;
    const float* vb = v + (size_t)b * S_ * D_ + h * DH_;
    float* cb = ctx + (size_t)b * S_ * D_ + h * DH_;

    const int tid = threadIdx.x, lane = tid & 31, warp = tid >> 5;
    const int g = lane >> 2, t = lane & 3;
    const int rowBase = qt * 128;
    const int wrow = warp * 16;

    // ---- Q prologue: each warp stages its own 16 rows, then keeps frags in regs
    #pragma unroll
    for (int u = 0; u < 8; u++) {
        int idx = u * 32 + lane;
        int r = idx >> 4, c4 = (idx & 15) * 4;
        cpasync16(&Ps[(wrow + r) * SK + c4],
                  &qb[(size_t)(rowBase + wrow + r) * D_ + c4]);
    }
    asm volatile("cp.async.commit_group;");
    asm volatile("cp.async.wait_group 0;");
    __syncwarp();

    unsigned qa[8][4];
    #pragma unroll
    for (int ks = 0; ks < 8; ks++) {
        qa[ks][0] = __float_as_uint(Ps[(wrow + g)     * SK + 8*ks + t]);
        qa[ks][1] = __float_as_uint(Ps[(wrow + g + 8) * SK + 8*ks + t]);
        qa[ks][2] = __float_as_uint(Ps[(wrow + g)     * SK + 8*ks + t + 4]);
        qa[ks][3] = __float_as_uint(Ps[(wrow + g + 8) * SK + 8*ks + t + 4]);
    }

    float o[8][4];
    #pragma unroll
    for (int nt = 0; nt < 8; nt++)
        #pragma unroll
        for (int e = 0; e < 4; e++) o[nt][e] = 0.f;
    float m0 = -1e30f, m1 = -1e30f, l0 = 0.f, l1 = 0.f;
    const int row0 = rowBase + wrow + g, row1 = row0 + 8;
    const int ktmax = 2 * qt + 2;

    for (int kt = 0; kt < ktmax; kt++) {
        __syncthreads();                      // Ks/Vs free
        #pragma unroll
        for (int u = 0; u < 4; u++) {
            int idx = u * 256 + tid;
            int r = idx >> 4, c4 = (idx & 15) * 4;
            cpasync16(&Ks[r * SK + c4], &kb[(size_t)(kt * 64 + r) * D_ + c4]);
            cpasync16(&Vs[r * SV + c4], &vb[(size_t)(kt * 64 + r) * D_ + c4]);
        }
        asm volatile("cp.async.commit_group;");
        asm volatile("cp.async.wait_group 0;");
        __syncthreads();                      // tiles visible

        // ---- S = (Q K^T) * 1/8, masked
        float sc[8][4];
        #pragma unroll
        for (int nt = 0; nt < 8; nt++) {
            sc[nt][0] = sc[nt][1] = sc[nt][2] = sc[nt][3] = 0.f;
            #pragma unroll
            for (int ks = 0; ks < 8; ks++) {
                unsigned bb[2];
                bb[0] = __float_as_uint(Ks[(8*nt + g) * SK + 8*ks + t]);
                bb[1] = __float_as_uint(Ks[(8*nt + g) * SK + 8*ks + t + 4]);
                mma_tf32(sc[nt], qa[ks], bb);
            }
        }

        float mx0 = -1e30f, mx1 = -1e30f;
        const int colb = kt * 64 + 2 * t;
        #pragma unroll
        for (int nt = 0; nt < 8; nt++) {
            int c0 = colb + 8 * nt;
            float v0 = sc[nt][0] * 0.125f; if (c0     > row0) v0 = -1e30f;
            float v1 = sc[nt][1] * 0.125f; if (c0 + 1 > row0) v1 = -1e30f;
            float v2 = sc[nt][2] * 0.125f; if (c0     > row1) v2 = -1e30f;
            float v3 = sc[nt][3] * 0.125f; if (c0 + 1 > row1) v3 = -1e30f;
            sc[nt][0] = v0; sc[nt][1] = v1; sc[nt][2] = v2; sc[nt][3] = v3;
            mx0 = fmaxf(mx0, fmaxf(v0, v1));
            mx1 = fmaxf(mx1, fmaxf(v2, v3));
        }
        mx0 = fmaxf(mx0, __shfl_xor_sync(0xffffffffu, mx0, 1));
        mx0 = fmaxf(mx0, __shfl_xor_sync(0xffffffffu, mx0, 2));
        mx1 = fmaxf(mx1, __shfl_xor_sync(0xffffffffu, mx1, 1));
        mx1 = fmaxf(mx1, __shfl_xor_sync(0xffffffffu, mx1, 2));

        float mn0 = fmaxf(m0, mx0), mn1 = fmaxf(m1, mx1);
        float s0 = __expf(m0 - mn0), s1 = __expf(m1 - mn1);
        m0 = mn0; m1 = mn1;

        float sum0 = 0.f, sum1 = 0.f;
        #pragma unroll
        for (int nt = 0; nt < 8; nt++) {
            float p0 = __expf(sc[nt][0] - mn0);
            float p1 = __expf(sc[nt][1] - mn0);
            float p2 = __expf(sc[nt][2] - mn1);
            float p3 = __expf(sc[nt][3] - mn1);
            sum0 += p0 + p1; sum1 += p2 + p3;
            *(float2*)&Ps[(wrow + g)     * SK + 8*nt + 2*t] =
                make_float2(rnd_tf32(p0), rnd_tf32(p1));
            *(float2*)&Ps[(wrow + g + 8) * SK + 8*nt + 2*t] =
                make_float2(rnd_tf32(p2), rnd_tf32(p3));
        }
        sum0 += __shfl_xor_sync(0xffffffffu, sum0, 1);
        sum0 += __shfl_xor_sync(0xffffffffu, sum0, 2);
        sum1 += __shfl_xor_sync(0xffffffffu, sum1, 1);
        sum1 += __shfl_xor_sync(0xffffffffu, sum1, 2);
        l0 = l0 * s0 + sum0;
        l1 = l1 * s1 + sum1;

        #pragma unroll
        for (int nt = 0; nt < 8; nt++) {
            o[nt][0] *= s0; o[nt][1] *= s0;
            o[nt][2] *= s1; o[nt][3] *= s1;
        }
        __syncwarp();                          // P visible within warp

        // ---- O += P @ V
        #pragma unroll
        for (int ks = 0; ks < 8; ks++) {
            unsigned pa[4];
            pa[0] = __float_as_uint(Ps[(wrow + g)     * SK + 8*ks + t]);
            pa[1] = __float_as_uint(Ps[(wrow + g + 8) * SK + 8*ks + t]);
            pa[2] = __float_as_uint(Ps[(wrow + g)     * SK + 8*ks + t + 4]);
            pa[3] = __float_as_uint(Ps[(wrow + g + 8) * SK + 8*ks + t + 4]);
            #pragma unroll
            for (int nt = 0; nt < 8; nt++) {
                unsigned bb[2];
                bb[0] = __float_as_uint(Vs[(8*ks + t)     * SV + 8*nt + g]);
                bb[1] = __float_as_uint(Vs[(8*ks + t + 4) * SV + 8*nt + g]);
                mma_tf32(o[nt], pa, bb);
            }
        }
    }

    // ---- epilogue: O / l, tf32-rounded (feeds O-proj GEMM)
    float inv0 = __fdividef(1.f, l0), inv1 = __fdividef(1.f, l1);
    #pragma unroll
    for (int nt = 0; nt < 8; nt++) {
        *(float2*)&cb[(size_t)row0 * D_ + 8*nt + 2*t] =
            make_float2(rnd_tf32(o[nt][0] * inv0), rnd_tf32(o[nt][1] * inv0));
        *(float2*)&cb[(size_t)row1 * D_ + 8*nt + 2*t] =
            make_float2(rnd_tf32(o[nt][2] * inv1), rnd_tf32(o[nt][3] * inv1));
    }
}

// ---------------- launcher -----------------------------------------------------
extern "C" void kernel_launch(void* const* d_in, const int* in_sizes, int n_in,
                              void* d_out, int out_size)
{
    const float* x     = (const float*)d_in[0];
    const float* ln1_s = (const float*)d_in[1];
    const float* ln1_b = (const float*)d_in[2];
    const float* wq    = (const float*)d_in[3];
    const float* wk    = (const float*)d_in[4];
    const float* wv    = (const float*)d_in[5];
    const float* wo    = (const float*)d_in[6];
    const float* bo    = (const float*)d_in[7];
    const float* ln2_s = (const float*)d_in[8];
    const float* ln2_b = (const float*)d_in[9];
    const float* w1    = (const float*)d_in[10];
    const float* b1    = (const float*)d_in[11];
    const float* w2    = (const float*)d_in[12];
    const float* b2    = (const float*)d_in[13];
    float* out = (float*)d_out;

    float *ln, *q, *k, *v, *ctx, *h, *ffn, *pool;
    cudaGetSymbolAddress((void**)&ln,   g_ln);
    cudaGetSymbolAddress((void**)&q,    g_q);
    cudaGetSymbolAddress((void**)&k,    g_k);
    cudaGetSymbolAddress((void**)&v,    g_v);
    cudaGetSymbolAddress((void**)&ctx,  g_ctx);
    cudaGetSymbolAddress((void**)&h,    g_h);
    cudaGetSymbolAddress((void**)&ffn,  g_ffn);
    cudaGetSymbolAddress((void**)&pool, g_pool);

    const int MB = 1024 * 1024;
    float* rwq = pool + 0 * MB;
    float* rwk = pool + 1 * MB;
    float* rwv = pool + 2 * MB;
    float* rwo = pool + 3 * MB;
    float* rw1 = pool + 4 * MB;   // 4 MB elements
    float* rw2 = pool + 8 * MB;   // 4 MB elements

    cudaFuncSetAttribute(flash_attn_kernel,
                         cudaFuncAttributeMaxDynamicSharedMemorySize, FLASH_SMEM);

    // 0) pre-round weights to tf32 (so GEMM inner loops carry zero converts)
    round_tf32_kernel<<<(D_*D_/4 + 255)/256, 256>>>(wq, rwq, D_*D_/4);
    round_tf32_kernel<<<(D_*D_/4 + 255)/256, 256>>>(wk, rwk, D_*D_/4);
    round_tf32_kernel<<<(D_*D_/4 + 255)/256, 256>>>(wv, rwv, D_*D_/4);
    round_tf32_kernel<<<(D_*D_/4 + 255)/256, 256>>>(wo, rwo, D_*D_/4);
    round_tf32_kernel<<<(D_*DFF_/4 + 255)/256, 256>>>(w1, rw1, D_*DFF_/4);
    round_tf32_kernel<<<(D_*DFF_/4 + 255)/256, 256>>>(w2, rw2, D_*DFF_/4);

    // 1) ln1(x) (tf32-rounded output)
    ln_kernel<<<M_, 256>>>(x, ln1_s, ln1_b, ln);

    // 2) q/k/v projections (outputs tf32-rounded for attention mma)
    dim3 gp(D_ / 128, M_ / 128);
    sgemm_tf32_kernel<<<gp, 256>>>(ln, rwq, nullptr, nullptr, q, M_, D_, D_, 0, 1);
    sgemm_tf32_kernel<<<gp, 256>>>(ln, rwk, nullptr, nullptr, k, M_, D_, D_, 0, 1);
    sgemm_tf32_kernel<<<gp, 256>>>(ln, rwv, nullptr, nullptr, v, M_, D_, D_, 0, 1);

    // 3) fused flash attention -> ctx (tf32-rounded)
    flash_attn_kernel<<<dim3(S_/128, B_*H_), 256, FLASH_SMEM>>>(q, k, v, ctx);

    // 4) output projection + bias + residual -> h (full precision)
    sgemm_tf32_kernel<<<gp, 256>>>(ctx, rwo, bo, x, h, M_, D_, D_, 0, 0);

    // 5) ln2(h) (tf32-rounded)
    ln_kernel<<<M_, 256>>>(h, ln2_s, ln2_b, ln);

    // 6) FFN
    dim3 gf1(DFF_ / 128, M_ / 128);
    sgemm_tf32_kernel<<<gf1, 256>>>(ln, rw1, b1, nullptr, ffn, M_, DFF_, D_, 1, 1);
    sgemm_tf32_kernel<<<gp, 256>>>(ffn, rw2, b2, h, out, M_, D_, DFF_, 0, 0);
}

// round 5
// speedup vs baseline: 4.7954x; 1.0417x over previous
#include <cuda_runtime.h>
#include <math.h>
#include <stdint.h>

#define B_   2
#define S_   2048
#define D_   1024
#define H_   16
#define DH_  64
#define DFF_ 4096
#define M_   (B_*S_)    // 4096 tokens
#define QKVD 3072

// ---------------- scratch (static device allocations) ---------------------------
__device__ float g_ln [M_ * D_];
__device__ float g_qkv[(size_t)M_ * QKVD];              // 48 MB
__device__ float g_ctx[M_ * D_];
__device__ float g_h  [M_ * D_];
__device__ float g_ffn[(size_t)M_ * DFF_];              // 64 MB
__device__ float g_pool[12 * 1024 * 1024];              // rounded weights

// ---------------- helpers --------------------------------------------------------
__device__ __forceinline__ unsigned f2tf32(float x) {
    unsigned r;
    asm("cvt.rna.tf32.f32 %0, %1;" : "=r"(r) : "f"(x));
    return r;
}
__device__ __forceinline__ float rnd_tf32(float x) {
    return __uint_as_float(f2tf32(x));
}
__device__ __forceinline__ void mma_tf32(float* c, const unsigned* a, const unsigned* b) {
    asm volatile(
        "mma.sync.aligned.m16n8k8.row.col.f32.tf32.tf32.f32 "
        "{%0,%1,%2,%3}, {%4,%5,%6,%7}, {%8,%9}, {%0,%1,%2,%3};"
        : "+f"(c[0]), "+f"(c[1]), "+f"(c[2]), "+f"(c[3])
        : "r"(a[0]), "r"(a[1]), "r"(a[2]), "r"(a[3]), "r"(b[0]), "r"(b[1]));
}
__device__ __forceinline__ void cpasync16(float* smem, const float* gmem) {
    unsigned s = (unsigned)__cvta_generic_to_shared(smem);
    asm volatile("cp.async.cg.shared.global [%0], [%1], 16;" :: "r"(s), "l"(gmem));
}

// ---------------- weight prep ----------------------------------------------------
__global__ void round_tf32_kernel(const float* __restrict__ in,
                                  float* __restrict__ out, int n4)
{
    int i = blockIdx.x * 256 + threadIdx.x;
    if (i < n4) {
        float4 a = ((const float4*)in)[i];
        a.x = rnd_tf32(a.x); a.y = rnd_tf32(a.y);
        a.z = rnd_tf32(a.z); a.w = rnd_tf32(a.w);
        ((float4*)out)[i] = a;
    }
}
// pack one [1024,1024] weight into columns [off, off+1024) of a [1024,3072] matrix
__global__ void pack_round_kernel(const float* __restrict__ in,
                                  float* __restrict__ out, int off4)
{
    int i = blockIdx.x * 256 + threadIdx.x;     // over 1024*256 float4s
    int k = i >> 8, n4 = i & 255;
    float4 a = ((const float4*)in)[i];
    a.x = rnd_tf32(a.x); a.y = rnd_tf32(a.y);
    a.z = rnd_tf32(a.z); a.w = rnd_tf32(a.w);
    ((float4*)(out + (size_t)k * QKVD))[off4 + n4] = a;
}

// ---------------- LayerNorm (output tf32-rounded) --------------------------------
__global__ void ln_kernel(const float* __restrict__ x,
                          const float* __restrict__ sc,
                          const float* __restrict__ sh,
                          float* __restrict__ out)
{
    int row = blockIdx.x;
    const float* xr = x + (size_t)row * D_;
    float* outr = out + (size_t)row * D_;

    float s = 0.f, s2 = 0.f;
    for (int j = threadIdx.x; j < D_; j += blockDim.x) {
        float v = xr[j];
        s += v; s2 += v * v;
    }
    __shared__ float rs[256], rs2[256];
    rs[threadIdx.x] = s; rs2[threadIdx.x] = s2;
    __syncthreads();
    for (int o = 128; o > 0; o >>= 1) {
        if (threadIdx.x < o) {
            rs [threadIdx.x] += rs [threadIdx.x + o];
            rs2[threadIdx.x] += rs2[threadIdx.x + o];
        }
        __syncthreads();
    }
    float mean = rs[0] * (1.0f / D_);
    float var  = rs2[0] * (1.0f / D_) - mean * mean;
    float inv  = rsqrtf(var + 1e-5f);
    for (int j = threadIdx.x; j < D_; j += blockDim.x)
        outr[j] = rnd_tf32((xr[j] - mean) * inv * sc[j] + sh[j]);
}

// ---------------- TF32 mma.sync GEMM, 4-stage cp.async, 1 sync/iter --------------
// C(MxN) = A(MxK) @ B(KxN), operands pre-rounded to tf32.
#define AS_STRIDE 20
#define BS_STRIDE 136
#define AS_BUF (128 * AS_STRIDE)          // floats
#define BS_BUF (16 * BS_STRIDE)
#define STG_FLOATS (AS_BUF + BS_BUF)      // 4736 floats = 18944 B
#define GSTAGES 4
#define GEMM_SMEM (GSTAGES * STG_FLOATS * 4)

__global__ __launch_bounds__(256, 2)
void sgemm_tf32_kernel(const float* __restrict__ A,
                       const float* __restrict__ Bm,
                       const float* __restrict__ bias,   // may be null
                       const float* __restrict__ res,    // may be null
                       float* __restrict__ C,
                       int M, int N, int K, int gelu, int roundOut)
{
    extern __shared__ float sm[];

    const int tid  = threadIdx.x;
    const int lane = tid & 31;
    const int warp = tid >> 5;
    const int g    = lane >> 2;
    const int t    = lane & 3;
    const int warpRow = warp >> 2;
    const int warpCol = warp & 3;

    const int rowBase = blockIdx.y * 128;
    const int colBase = blockIdx.x * 128;

    float acc[4][4][4];
    #pragma unroll
    for (int i = 0; i < 4; i++)
        #pragma unroll
        for (int j = 0; j < 4; j++)
            #pragma unroll
            for (int r = 0; r < 4; r++) acc[i][j][r] = 0.f;

    const int nIter = K / 16;

    // prefetch helper indices
    const int arr = tid >> 2, akc = (tid & 3) * 4;          // A: 2 chunks/thread
    const int brr = tid >> 5, bnc = (tid & 31) * 4;          // B: 2 chunks/thread

    // prologue: stages 0..2
    #pragma unroll
    for (int p = 0; p < GSTAGES - 1; p++) {
        float* As = sm + p * STG_FLOATS;
        float* Bs = As + AS_BUF;
        int k0 = p * 16;
        cpasync16(&As[arr * AS_STRIDE + akc],        &A[(size_t)(rowBase + arr) * K + k0 + akc]);
        cpasync16(&As[(arr + 64) * AS_STRIDE + akc], &A[(size_t)(rowBase + arr + 64) * K + k0 + akc]);
        cpasync16(&Bs[brr * BS_STRIDE + bnc],        &Bm[(size_t)(k0 + brr) * N + colBase + bnc]);
        cpasync16(&Bs[(brr + 8) * BS_STRIDE + bnc],  &Bm[(size_t)(k0 + brr + 8) * N + colBase + bnc]);
        asm volatile("cp.async.commit_group;");
    }

    for (int kt = 0; kt < nIter; ++kt) {
        // wait for tile kt (keep at most the newer prefetches pending)
        if (kt + 3 <= nIter)      { asm volatile("cp.async.wait_group 2;"); }
        else if (kt + 2 == nIter) { asm volatile("cp.async.wait_group 1;"); }
        else                      { asm volatile("cp.async.wait_group 0;"); }
        __syncthreads();

        // prefetch tile kt+3 into stage (kt+3)%4 (== stage consumed at iter kt-1)
        if (kt + 3 < nIter) {
            int st = (kt + 3) & 3;
            float* As = sm + st * STG_FLOATS;
            float* Bs = As + AS_BUF;
            int k0 = (kt + 3) * 16;
            cpasync16(&As[arr * AS_STRIDE + akc],        &A[(size_t)(rowBase + arr) * K + k0 + akc]);
            cpasync16(&As[(arr + 64) * AS_STRIDE + akc], &A[(size_t)(rowBase + arr + 64) * K + k0 + akc]);
            cpasync16(&Bs[brr * BS_STRIDE + bnc],        &Bm[(size_t)(k0 + brr) * N + colBase + bnc]);
            cpasync16(&Bs[(brr + 8) * BS_STRIDE + bnc],  &Bm[(size_t)(k0 + brr + 8) * N + colBase + bnc]);
            asm volatile("cp.async.commit_group;");
        }

        const float* As_ = sm + (kt & 3) * STG_FLOATS;
        const float* Bs_ = As_ + AS_BUF;

        #pragma unroll
        for (int ks = 0; ks < 2; ks++) {
            const int k = ks * 8;
            unsigned afr[4][4], bfr[4][2];
            #pragma unroll
            for (int mt = 0; mt < 4; mt++) {
                int m = warpRow * 64 + mt * 16 + g;
                afr[mt][0] = __float_as_uint(As_[m * AS_STRIDE + k + t]);
                afr[mt][1] = __float_as_uint(As_[(m + 8) * AS_STRIDE + k + t]);
                afr[mt][2] = __float_as_uint(As_[m * AS_STRIDE + k + t + 4]);
                afr[mt][3] = __float_as_uint(As_[(m + 8) * AS_STRIDE + k + t + 4]);
            }
            #pragma unroll
            for (int nt = 0; nt < 4; nt++) {
                int n = warpCol * 32 + nt * 8 + g;
                bfr[nt][0] = __float_as_uint(Bs_[(k + t) * BS_STRIDE + n]);
                bfr[nt][1] = __float_as_uint(Bs_[(k + t + 4) * BS_STRIDE + n]);
            }
            #pragma unroll
            for (int mt = 0; mt < 4; mt++)
                #pragma unroll
                for (int nt = 0; nt < 4; nt++)
                    mma_tf32(acc[mt][nt], afr[mt], bfr[nt]);
        }
    }

    #pragma unroll
    for (int mt = 0; mt < 4; mt++) {
        #pragma unroll
        for (int nt = 0; nt < 4; nt++) {
            int r0 = rowBase + warpRow * 64 + mt * 16 + g;
            int c0 = colBase + warpCol * 32 + nt * 8 + 2 * t;
            #pragma unroll
            for (int e = 0; e < 4; e++) {
                int r = r0 + (e >> 1) * 8;
                int c = c0 + (e & 1);
                float v = acc[mt][nt][e];
                if (bias) v += bias[c];
                if (gelu) {
                    float tt = 1.5957691216057308f * v + 0.0713548162726009f * v * v * v;
                    v = __fdividef(v, 1.f + __expf(-tt));
                }
                if (res) v += res[(size_t)r * N + c];
                if (roundOut) v = rnd_tf32(v);
                C[(size_t)r * N + c] = v;
            }
        }
    }
}

// ---------------- fused flash attention (causal, tf32 mma.sync) ------------------
// K/V double-buffered with prefetch-next-tile overlap. Q scaled by 1/8 in frags.
#define SK 68
#define SV 72
#define KVBUF (64*SK + 64*SV)
#define FLASH_SMEM ((128*SK + 2*KVBUF) * 4)

__global__ __launch_bounds__(256)
void flash_attn_kernel(const float* __restrict__ qkv, float* __restrict__ ctx)
{
    extern __shared__ float sm[];
    float* Ps = sm;                       // 128 x SK (Q prologue, then P)
    float* KV0 = sm + 128 * SK;           // double-buffered K/V tiles

    const int qt = (int)(gridDim.x - 1) - (int)blockIdx.x;   // big tiles first
    const int bh = blockIdx.y;
    const int b = bh >> 4, h = bh & 15;
    const float* qb = qkv + (size_t)b * S_ * QKVD + h * DH_;
    const float* kb = qb + D_;
    const float* vb = qb + 2 * D_;
    float* cb = ctx + (size_t)b * S_ * D_ + h * DH_;

    const int tid = threadIdx.x, lane = tid & 31, warp = tid >> 5;
    const int g = lane >> 2, t = lane & 3;
    const int rowBase = qt * 128;
    const int wrow = warp * 16;
    const int ktmax = 2 * qt + 2;

    // ---- Q prologue
    #pragma unroll
    for (int u = 0; u < 8; u++) {
        int idx = u * 32 + lane;
        int r = idx >> 4, c4 = (idx & 15) * 4;
        cpasync16(&Ps[(wrow + r) * SK + c4],
                  &qb[(size_t)(rowBase + wrow + r) * QKVD + c4]);
    }
    asm volatile("cp.async.commit_group;");
    asm volatile("cp.async.wait_group 0;");
    __syncwarp();

    unsigned qa[8][4];
    #pragma unroll
    for (int ks = 0; ks < 8; ks++) {
        qa[ks][0] = __float_as_uint(0.125f * Ps[(wrow + g)     * SK + 8*ks + t]);
        qa[ks][1] = __float_as_uint(0.125f * Ps[(wrow + g + 8) * SK + 8*ks + t]);
        qa[ks][2] = __float_as_uint(0.125f * Ps[(wrow + g)     * SK + 8*ks + t + 4]);
        qa[ks][3] = __float_as_uint(0.125f * Ps[(wrow + g + 8) * SK + 8*ks + t + 4]);
    }

    // ---- prefetch KV tile 0 into buffer 0
    {
        float* Ks = KV0;
        float* Vs = KV0 + 64 * SK;
        #pragma unroll
        for (int u = 0; u < 4; u++) {
            int idx = u * 256 + tid;
            int r = idx >> 4, c4 = (idx & 15) * 4;
            cpasync16(&Ks[r * SK + c4], &kb[(size_t)r * QKVD + c4]);
            cpasync16(&Vs[r * SV + c4], &vb[(size_t)r * QKVD + c4]);
        }
        asm volatile("cp.async.commit_group;");
    }

    float o[8][4];
    #pragma unroll
    for (int nt = 0; nt < 8; nt++)
        #pragma unroll
        for (int e = 0; e < 4; e++) o[nt][e] = 0.f;
    float m0 = -1e30f, m1 = -1e30f, l0 = 0.f, l1 = 0.f;
    const int row0 = rowBase + wrow + g, row1 = row0 + 8;

    for (int kt = 0; kt < ktmax; kt++) {
        __syncthreads();                       // prev compute done on buf^1
        if (kt + 1 < ktmax) {                  // prefetch next tile into buf^1
            float* Ks = KV0 + ((kt + 1) & 1) * KVBUF;
            float* Vs = Ks + 64 * SK;
            #pragma unroll
            for (int u = 0; u < 4; u++) {
                int idx = u * 256 + tid;
                int r = idx >> 4, c4 = (idx & 15) * 4;
                cpasync16(&Ks[r * SK + c4], &kb[(size_t)((kt + 1) * 64 + r) * QKVD + c4]);
                cpasync16(&Vs[r * SV + c4], &vb[(size_t)((kt + 1) * 64 + r) * QKVD + c4]);
            }
            asm volatile("cp.async.commit_group;");
            asm volatile("cp.async.wait_group 1;");
        } else {
            asm volatile("cp.async.wait_group 0;");
        }
        __syncthreads();                       // tile kt visible to all

        const float* Ks = KV0 + (kt & 1) * KVBUF;
        const float* Vs = Ks + 64 * SK;

        // ---- S = Q K^T (Q pre-scaled)
        float sc[8][4];
        #pragma unroll
        for (int nt = 0; nt < 8; nt++) {
            sc[nt][0] = sc[nt][1] = sc[nt][2] = sc[nt][3] = 0.f;
            #pragma unroll
            for (int ks = 0; ks < 8; ks++) {
                unsigned bb[2];
                bb[0] = __float_as_uint(Ks[(8*nt + g) * SK + 8*ks + t]);
                bb[1] = __float_as_uint(Ks[(8*nt + g) * SK + 8*ks + t + 4]);
                mma_tf32(sc[nt], qa[ks], bb);
            }
        }

        float mx0 = -1e30f, mx1 = -1e30f;
        const int colb = kt * 64 + 2 * t;
        #pragma unroll
        for (int nt = 0; nt < 8; nt++) {
            int c0 = colb + 8 * nt;
            float v0 = sc[nt][0]; if (c0     > row0) v0 = -1e30f;
            float v1 = sc[nt][1]; if (c0 + 1 > row0) v1 = -1e30f;
            float v2 = sc[nt][2]; if (c0     > row1) v2 = -1e30f;
            float v3 = sc[nt][3]; if (c0 + 1 > row1) v3 = -1e30f;
            sc[nt][0] = v0; sc[nt][1] = v1; sc[nt][2] = v2; sc[nt][3] = v3;
            mx0 = fmaxf(mx0, fmaxf(v0, v1));
            mx1 = fmaxf(mx1, fmaxf(v2, v3));
        }
        mx0 = fmaxf(mx0, __shfl_xor_sync(0xffffffffu, mx0, 1));
        mx0 = fmaxf(mx0, __shfl_xor_sync(0xffffffffu, mx0, 2));
        mx1 = fmaxf(mx1, __shfl_xor_sync(0xffffffffu, mx1, 1));
        mx1 = fmaxf(mx1, __shfl_xor_sync(0xffffffffu, mx1, 2));

        float mn0 = fmaxf(m0, mx0), mn1 = fmaxf(m1, mx1);
        float s0 = __expf(m0 - mn0), s1 = __expf(m1 - mn1);
        m0 = mn0; m1 = mn1;

        float sum0 = 0.f, sum1 = 0.f;
        #pragma unroll
        for (int nt = 0; nt < 8; nt++) {
            float p0 = __expf(sc[nt][0] - mn0);
            float p1 = __expf(sc[nt][1] - mn0);
            float p2 = __expf(sc[nt][2] - mn1);
            float p3 = __expf(sc[nt][3] - mn1);
            sum0 += p0 + p1; sum1 += p2 + p3;
            *(float2*)&Ps[(wrow + g)     * SK + 8*nt + 2*t] =
                make_float2(rnd_tf32(p0), rnd_tf32(p1));
            *(float2*)&Ps[(wrow + g + 8) * SK + 8*nt + 2*t] =
                make_float2(rnd_tf32(p2), rnd_tf32(p3));
        }
        sum0 += __shfl_xor_sync(0xffffffffu, sum0, 1);
        sum0 += __shfl_xor_sync(0xffffffffu, sum0, 2);
        sum1 += __shfl_xor_sync(0xffffffffu, sum1, 1);
        sum1 += __shfl_xor_sync(0xffffffffu, sum1, 2);
        l0 = l0 * s0 + sum0;
        l1 = l1 * s1 + sum1;

        #pragma unroll
        for (int nt = 0; nt < 8; nt++) {
            o[nt][0] *= s0; o[nt][1] *= s0;
            o[nt][2] *= s1; o[nt][3] *= s1;
        }
        __syncwarp();                          // P visible within warp

        // ---- O += P @ V
        #pragma unroll
        for (int ks = 0; ks < 8; ks++) {
            unsigned pa[4];
            pa[0] = __float_as_uint(Ps[(wrow + g)     * SK + 8*ks + t]);
            pa[1] = __float_as_uint(Ps[(wrow + g + 8) * SK + 8*ks + t]);
            pa[2] = __float_as_uint(Ps[(wrow + g)     * SK + 8*ks + t + 4]);
            pa[3] = __float_as_uint(Ps[(wrow + g + 8) * SK + 8*ks + t + 4]);
            #pragma unroll
            for (int nt = 0; nt < 8; nt++) {
                unsigned bb[2];
                bb[0] = __float_as_uint(Vs[(8*ks + t)     * SV + 8*nt + g]);
                bb[1] = __float_as_uint(Vs[(8*ks + t + 4) * SV + 8*nt + g]);
                mma_tf32(o[nt], pa, bb);
            }
        }
    }

    float inv0 = __fdividef(1.f, l0), inv1 = __fdividef(1.f, l1);
    #pragma unroll
    for (int nt = 0; nt < 8; nt++) {
        *(float2*)&cb[(size_t)row0 * D_ + 8*nt + 2*t] =
            make_float2(rnd_tf32(o[nt][0] * inv0), rnd_tf32(o[nt][1] * inv0));
        *(float2*)&cb[(size_t)row1 * D_ + 8*nt + 2*t] =
            make_float2(rnd_tf32(o[nt][2] * inv1), rnd_tf32(o[nt][3] * inv1));
    }
}

// ---------------- launcher -------------------------------------------------------
extern "C" void kernel_launch(void* const* d_in, const int* in_sizes, int n_in,
                              void* d_out, int out_size)
{
    const float* x     = (const float*)d_in[0];
    const float* ln1_s = (const float*)d_in[1];
    const float* ln1_b = (const float*)d_in[2];
    const float* wq    = (const float*)d_in[3];
    const float* wk    = (const float*)d_in[4];
    const float* wv    = (const float*)d_in[5];
    const float* wo    = (const float*)d_in[6];
    const float* bo    = (const float*)d_in[7];
    const float* ln2_s = (const float*)d_in[8];
    const float* ln2_b = (const float*)d_in[9];
    const float* w1    = (const float*)d_in[10];
    const float* b1    = (const float*)d_in[11];
    const float* w2    = (const float*)d_in[12];
    const float* b2    = (const float*)d_in[13];
    float* out = (float*)d_out;

    float *ln, *qkv, *ctx, *h, *ffn, *pool;
    cudaGetSymbolAddress((void**)&ln,   g_ln);
    cudaGetSymbolAddress((void**)&qkv,  g_qkv);
    cudaGetSymbolAddress((void**)&ctx,  g_ctx);
    cudaGetSymbolAddress((void**)&h,    g_h);
    cudaGetSymbolAddress((void**)&ffn,  g_ffn);
    cudaGetSymbolAddress((void**)&pool, g_pool);

    const int MB = 1024 * 1024;
    float* wqkvP = pool + 0 * MB;   // [1024, 3072]
    float* rwo   = pool + 3 * MB;
    float* rw1   = pool + 4 * MB;   // [1024, 4096]
    float* rw2   = pool + 8 * MB;   // [4096, 1024]

    cudaFuncSetAttribute(flash_attn_kernel,
                         cudaFuncAttributeMaxDynamicSharedMemorySize, FLASH_SMEM);
    cudaFuncSetAttribute(sgemm_tf32_kernel,
                         cudaFuncAttributeMaxDynamicSharedMemorySize, GEMM_SMEM);

    // 0) weight prep: pack QKV [1024,3072], round others
    pack_round_kernel<<<1024, 256>>>(wq, wqkvP, 0);
    pack_round_kernel<<<1024, 256>>>(wk, wqkvP, 256);
    pack_round_kernel<<<1024, 256>>>(wv, wqkvP, 512);
    round_tf32_kernel<<<(D_*D_/4 + 255)/256, 256>>>(wo, rwo, D_*D_/4);
    round_tf32_kernel<<<(D_*DFF_/4 + 255)/256, 256>>>(w1, rw1, D_*DFF_/4);
    round_tf32_kernel<<<(D_*DFF_/4 + 255)/256, 256>>>(w2, rw2, D_*DFF_/4);

    // 1) ln1(x)
    ln_kernel<<<M_, 256>>>(x, ln1_s, ln1_b, ln);

    // 2) fused QKV projection (one GEMM, N=3072), output tf32-rounded
    dim3 gqkv(QKVD / 128, M_ / 128);
    sgemm_tf32_kernel<<<gqkv, 256, GEMM_SMEM>>>(ln, wqkvP, nullptr, nullptr, qkv,
                                                M_, QKVD, D_, 0, 1);

    // 3) fused flash attention -> ctx (tf32-rounded)
    flash_attn_kernel<<<dim3(S_/128, B_*H_), 256, FLASH_SMEM>>>(qkv, ctx);

    // 4) output projection + bias + residual -> h
    dim3 gp(D_ / 128, M_ / 128);
    sgemm_tf32_kernel<<<gp, 256, GEMM_SMEM>>>(ctx, rwo, bo, x, h, M_, D_, D_, 0, 0);

    // 5) ln2(h)
    ln_kernel<<<M_, 256>>>(h, ln2_s, ln2_b, ln);

    // 6) FFN
    dim3 gf1(DFF_ / 128, M_ / 128);
    sgemm_tf32_kernel<<<gf1, 256, GEMM_SMEM>>>(ln, rw1, b1, nullptr, ffn, M_, DFF_, D_, 1, 1);
    sgemm_tf32_kernel<<<gp, 256, GEMM_SMEM>>>(ffn, rw2, b2, h, out, M_, D_, DFF_, 0, 0);
}